// round 1
// baseline (speedup 1.0000x reference)
#include <cuda_runtime.h>
#include <math.h>

// TwoLayerNetwork: ConstantCurrentLIFEncoder -> LIFCell -> LILinearCell, T=32,
// then max over timesteps and log_softmax.
//
// Constants from reference:
//   DT*TAU_MEM_INV = 0.1   -> membrane decay 0.9
//   DT*TAU_SYN_INV = 0.2   -> synapse decay 0.8
//   V_TH = 1.0
//
// Design: one warp per batch element (4096 warps). Each lane owns 25 neurons
// (j = lane + 32*i, phantom-padded past 784 with x=0 which can never spike).
// The 784-dim dynamics are lane-local in registers; the 10-dim output layer
// needs cross-lane data ONLY when a hidden spike fires that timestep, which is
// detected with __any_sync and handled by a rare slow path (masked W gather +
// warp reduction). No shared memory, no block syncs.

#define NT 32
#define NPL 25   // neurons per lane (25*32 = 800 >= 784)

__global__ __launch_bounds__(128) void snn_kernel(
    const float* __restrict__ image,   // [4096, 784]
    const float* __restrict__ W,       // [10, 784]
    float* __restrict__ out)           // [4096, 10]
{
    const int lane = threadIdx.x & 31;
    const int b = blockIdx.x * 4 + (threadIdx.x >> 5);

    const float* x = image + (size_t)b * 784;

    float xs[NPL];   // 0.1 * x
    float ve[NPL];   // encoder membrane
    float v0[NPL];   // hidden membrane
    float i0[NPL];   // hidden synaptic current
#pragma unroll
    for (int i = 0; i < NPL; i++) {
        const int j = lane + 32 * i;
        xs[i] = (j < 784) ? 0.1f * __ldg(&x[j]) : 0.0f;
        ve[i] = 0.0f;
        v0[i] = 0.0f;
        i0[i] = 0.0f;
    }

    float v_out = 0.0f, i_out = 0.0f, vmax = -INFINITY;

#pragma unroll 1
    for (int t = 0; t < NT; t++) {
        unsigned tmask = 0u;   // which of this lane's neurons fired z0 this step
#pragma unroll
        for (int i = 0; i < NPL; i++) {
            // encoder LIF step
            float v = fmaf(ve[i], 0.9f, xs[i]);
            const bool pe = (v > 1.0f);
            const float zef = pe ? 1.0f : 0.0f;
            ve[i] = pe ? 0.0f : v;
            // hidden LIF step (reads old v0, i0)
            const float vd = fmaf(v0[i], 0.9f, 0.1f * i0[i]);
            const bool p0 = (vd > 1.0f);
            v0[i] = p0 ? 0.0f : vd;
            i0[i] = fmaf(i0[i], 0.8f, zef);
            if (p0) tmask |= (1u << i);
        }

        // s[k] = sum_j z0[j] * W[k, j]; zero on the (common) spike-free path.
        float s = 0.0f;
        if (__any_sync(0xffffffffu, tmask != 0u)) {
            float acc[10];
#pragma unroll
            for (int k = 0; k < 10; k++) acc[k] = 0.0f;
            unsigned m = tmask;
            while (m) {
                const int i = __ffs(m) - 1;
                m &= (m - 1u);
                const int j = lane + 32 * i;
#pragma unroll
                for (int k = 0; k < 10; k++)
                    acc[k] += __ldg(&W[k * 784 + j]);
            }
#pragma unroll
            for (int k = 0; k < 10; k++) {
#pragma unroll
                for (int off = 16; off; off >>= 1)
                    acc[k] += __shfl_xor_sync(0xffffffffu, acc[k], off);
            }
            // pick acc[lane] without dynamic indexing (avoids local-mem spill)
            s = acc[0];
#pragma unroll
            for (int k = 1; k < 10; k++) s = (lane == k) ? acc[k] : s;
        }

        // LILinearCell recurrence (valid on lanes 0..9; others harmless)
        const float i_jump = i_out + s;
        v_out = fmaf(v_out, 0.9f, 0.1f * i_jump);
        i_out = 0.8f * i_jump;
        vmax = fmaxf(vmax, v_out);
    }

    // log_softmax over the 10 classes held by lanes 0..9
    const float v = (lane < 10) ? vmax : -INFINITY;
    float mred = v;
#pragma unroll
    for (int off = 16; off; off >>= 1)
        mred = fmaxf(mred, __shfl_xor_sync(0xffffffffu, mred, off));
    float e = (lane < 10) ? expf(v - mred) : 0.0f;
    float se = e;
#pragma unroll
    for (int off = 16; off; off >>= 1)
        se += __shfl_xor_sync(0xffffffffu, se, off);

    if (lane < 10)
        out[(size_t)b * 10 + lane] = v - mred - logf(se);
}

extern "C" void kernel_launch(void* const* d_in, const int* in_sizes, int n_in,
                              void* d_out, int out_size) {
    const float* image = (const float*)d_in[0];  // [4096,1,28,28] fp32
    const float* W     = (const float*)d_in[1];  // [10,784] fp32
    float* out         = (float*)d_out;          // [4096,10] fp32
    (void)in_sizes; (void)n_in; (void)out_size;

    snn_kernel<<<1024, 128>>>(image, W, out);
}

// round 2
// speedup vs baseline: 7.2609x; 7.2609x over previous
#include <cuda_runtime.h>
#include <math.h>

// TwoLayerNetwork: ConstantCurrentLIFEncoder -> LIFCell -> LILinearCell, T=32,
// then max over timesteps and log_softmax.
//
// Constants from reference:
//   DT*TAU_MEM_INV = 0.1   -> membrane decay 0.9
//   DT*TAU_SYN_INV = 0.2   -> synapse decay 0.8
//   V_TH = 1.0
//
// Design: one warp per batch element (4096 warps). Each lane owns 25 neurons
// (j = lane + 32*i, phantom-padded past 784 with x=0 which can never spike).
//
// EXACT per-row fast path: v_enc follows v' = 0.9 v + 0.1 x from 0, so
// v_enc <= max_j x_j for all t. A spike needs v_enc > 1.0, so if ALL pixels
// of this row are <= 1.0 the row provably never spikes anywhere downstream:
// v_out stays identically 0 and the answer is log_softmax(zeros) = -log(10).
// Rows containing a pixel > 1.0 run the full general dynamics below
// (unchanged from the R1 kernel that passed with rel_err = 0).

#define NT 32
#define NPL 25   // neurons per lane (25*32 = 800 >= 784)

__global__ __launch_bounds__(128) void snn_kernel(
    const float* __restrict__ image,   // [4096, 784]
    const float* __restrict__ W,       // [10, 784]
    float* __restrict__ out)           // [4096, 10]
{
    const int lane = threadIdx.x & 31;
    const int b = blockIdx.x * 4 + (threadIdx.x >> 5);

    const float* x = image + (size_t)b * 784;

    float xs[NPL];   // 0.1 * x
    bool hot = false;
#pragma unroll
    for (int i = 0; i < NPL; i++) {
        const int j = lane + 32 * i;
        const float xv = (j < 784) ? __ldg(&x[j]) : 0.0f;
        hot |= (xv > 1.0f);
        xs[i] = 0.1f * xv;
    }

    // Fast path: this row can never produce a spike -> output is -log(10).
    if (!__any_sync(0xffffffffu, hot)) {
        if (lane < 10)
            out[(size_t)b * 10 + lane] = -2.302585093f;  // log_softmax(0..0)
        return;
    }

    // ---- Full general simulation (identical to the verified R1 path) ----
    float ve[NPL];   // encoder membrane
    float v0[NPL];   // hidden membrane
    float i0[NPL];   // hidden synaptic current
#pragma unroll
    for (int i = 0; i < NPL; i++) { ve[i] = 0.0f; v0[i] = 0.0f; i0[i] = 0.0f; }

    float v_out = 0.0f, i_out = 0.0f, vmax = -INFINITY;

#pragma unroll 1
    for (int t = 0; t < NT; t++) {
        unsigned tmask = 0u;   // which of this lane's neurons fired z0 this step
#pragma unroll
        for (int i = 0; i < NPL; i++) {
            // encoder LIF step
            float v = fmaf(ve[i], 0.9f, xs[i]);
            const bool pe = (v > 1.0f);
            const float zef = pe ? 1.0f : 0.0f;
            ve[i] = pe ? 0.0f : v;
            // hidden LIF step (reads old v0, i0)
            const float vd = fmaf(v0[i], 0.9f, 0.1f * i0[i]);
            const bool p0 = (vd > 1.0f);
            v0[i] = p0 ? 0.0f : vd;
            i0[i] = fmaf(i0[i], 0.8f, zef);
            if (p0) tmask |= (1u << i);
        }

        // s[k] = sum_j z0[j] * W[k, j]; zero on the spike-free step.
        float s = 0.0f;
        if (__any_sync(0xffffffffu, tmask != 0u)) {
            float acc[10];
#pragma unroll
            for (int k = 0; k < 10; k++) acc[k] = 0.0f;
            unsigned m = tmask;
            while (m) {
                const int i = __ffs(m) - 1;
                m &= (m - 1u);
                const int j = lane + 32 * i;
#pragma unroll
                for (int k = 0; k < 10; k++)
                    acc[k] += __ldg(&W[k * 784 + j]);
            }
#pragma unroll
            for (int k = 0; k < 10; k++) {
#pragma unroll
                for (int off = 16; off; off >>= 1)
                    acc[k] += __shfl_xor_sync(0xffffffffu, acc[k], off);
            }
            // pick acc[lane] without dynamic indexing (avoids local-mem spill)
            s = acc[0];
#pragma unroll
            for (int k = 1; k < 10; k++) s = (lane == k) ? acc[k] : s;
        }

        // LILinearCell recurrence (valid on lanes 0..9; others harmless)
        const float i_jump = i_out + s;
        v_out = fmaf(v_out, 0.9f, 0.1f * i_jump);
        i_out = 0.8f * i_jump;
        vmax = fmaxf(vmax, v_out);
    }

    // log_softmax over the 10 classes held by lanes 0..9
    const float v = (lane < 10) ? vmax : -INFINITY;
    float mred = v;
#pragma unroll
    for (int off = 16; off; off >>= 1)
        mred = fmaxf(mred, __shfl_xor_sync(0xffffffffu, mred, off));
    float e = (lane < 10) ? expf(v - mred) : 0.0f;
    float se = e;
#pragma unroll
    for (int off = 16; off; off >>= 1)
        se += __shfl_xor_sync(0xffffffffu, se, off);

    if (lane < 10)
        out[(size_t)b * 10 + lane] = v - mred - logf(se);
}

extern "C" void kernel_launch(void* const* d_in, const int* in_sizes, int n_in,
                              void* d_out, int out_size) {
    const float* image = (const float*)d_in[0];  // [4096,1,28,28] fp32
    const float* W     = (const float*)d_in[1];  // [10,784] fp32
    float* out         = (float*)d_out;          // [4096,10] fp32
    (void)in_sizes; (void)n_in; (void)out_size;

    snn_kernel<<<1024, 128>>>(image, W, out);
}